// round 1
// baseline (speedup 1.0000x reference)
#include <cuda_runtime.h>

#define BN 8
#define CC 64
#define MM 256
#define NNX 256
#define MN (MM*NNX)          // 65536
#define TOTPIX (BN*MN)       // 524288

__device__ float g_avg[TOTPIX];
__device__ float g_mx [TOTPIX];
__device__ float g_sa [TOTPIX];
__device__ float g_gam[TOTPIX];
__device__ float g_bet[TOTPIX];
__device__ unsigned char g_mask[TOTPIX];
__device__ double g_stats[CC*4];      // s1, q1, s2, q2 per channel
__device__ unsigned int g_np;
__device__ float g_params[CC*4];      // mu1, a1, mu2, a2 per channel

// ---------------- K0: zero accumulators ----------------
__global__ void k0_zero() {
    int t = threadIdx.x;
    if (t < CC*4) g_stats[t] = 0.0;
    if (t == 0)   g_np = 0u;
}

// ---------------- K1: channel avg + max ----------------
__global__ void k1_avgmax(const float* __restrict__ x) {
    int tid  = blockIdx.x * blockDim.x + threadIdx.x;
    int base = tid * 4;                       // pixel index over (B, M*N)
    int b    = base >> 16;
    int pix  = base & (MN - 1);
    const float* xb = x + ((size_t)b << 22) + pix;

    float4 s  = *(const float4*)(xb);
    float4 mx = s;
#pragma unroll 8
    for (int c = 1; c < CC; c++) {
        float4 v = *(const float4*)(xb + ((size_t)c << 16));
        s.x += v.x; s.y += v.y; s.z += v.z; s.w += v.w;
        mx.x = fmaxf(mx.x, v.x); mx.y = fmaxf(mx.y, v.y);
        mx.z = fmaxf(mx.z, v.z); mx.w = fmaxf(mx.w, v.w);
    }
    float4 a;
    const float inv = 1.0f / 64.0f;
    a.x = s.x * inv; a.y = s.y * inv; a.z = s.z * inv; a.w = s.w * inv;
    *(float4*)(g_avg + base) = a;
    *(float4*)(g_mx  + base) = mx;
}

// ---------------- K2: sa_map = sigmoid(conv7x7([avg,max], w1)) ----------------
__global__ void k2_samap(const float* __restrict__ w1) {
    __shared__ float sA[14][40];
    __shared__ float sM[14][40];
    __shared__ float sw[98];
    const int b  = blockIdx.z;
    const int x0 = blockIdx.x * 32, y0 = blockIdx.y * 8;
    const int t  = threadIdx.y * 32 + threadIdx.x;
    if (t < 98) sw[t] = w1[t];
    const float* A = g_avg + b * MN;
    const float* X = g_mx  + b * MN;
    for (int i = t; i < 14 * 38; i += 256) {
        int sy = i / 38, sx = i % 38;
        int gy = y0 + sy - 3, gx = x0 + sx - 3;
        float a = 0.f, m = 0.f;
        if ((unsigned)gy < 256u && (unsigned)gx < 256u) {
            int g = gy * 256 + gx; a = A[g]; m = X[g];
        }
        sA[sy][sx] = a; sM[sy][sx] = m;
    }
    __syncthreads();
    int ty = threadIdx.y, tx = threadIdx.x;
    float acc = 0.f;
#pragma unroll
    for (int ky = 0; ky < 7; ky++)
#pragma unroll
        for (int kx = 0; kx < 7; kx++) {
            acc = fmaf(sA[ty + ky][tx + kx], sw[ky * 7 + kx], acc);
            acc = fmaf(sM[ty + ky][tx + kx], sw[49 + ky * 7 + kx], acc);
        }
    float s = 1.f / (1.f + expf(-acc));
    g_sa[b * MN + (y0 + ty) * 256 + x0 + tx] = s;
}

// ---------------- K3: gamma/beta convs + mask + Np count ----------------
__global__ void k3_gb(const float* __restrict__ wg, const float* __restrict__ bg,
                      const float* __restrict__ wb, const float* __restrict__ bb) {
    __shared__ float sS[14][40];
    __shared__ float swg[49], swb[49];
    __shared__ int scount[8];
    const int b  = blockIdx.z;
    const int x0 = blockIdx.x * 32, y0 = blockIdx.y * 8;
    const int t  = threadIdx.y * 32 + threadIdx.x;
    if (t < 49) { swg[t] = wg[t]; swb[t] = wb[t]; }
    const float* S = g_sa + b * MN;
    for (int i = t; i < 14 * 38; i += 256) {
        int sy = i / 38, sx = i % 38;
        int gy = y0 + sy - 3, gx = x0 + sx - 3;
        float v = 0.f;
        if ((unsigned)gy < 256u && (unsigned)gx < 256u) v = S[gy * 256 + gx];
        sS[sy][sx] = v;
    }
    __syncthreads();
    int ty = threadIdx.y, tx = threadIdx.x;
    float ag = 0.f, ab = 0.f;
#pragma unroll
    for (int ky = 0; ky < 7; ky++)
#pragma unroll
        for (int kx = 0; kx < 7; kx++) {
            float v = sS[ty + ky][tx + kx];
            ag = fmaf(v, swg[ky * 7 + kx], ag);
            ab = fmaf(v, swb[ky * 7 + kx], ab);
        }
    int idx = b * MN + (y0 + ty) * 256 + x0 + tx;
    g_gam[idx] = ag + bg[0];
    g_bet[idx] = ab + bb[0];
    int mk = (sS[ty + 3][tx + 3] >= 0.8f) ? 1 : 0;
    g_mask[idx] = (unsigned char)mk;
    unsigned bal = __ballot_sync(0xffffffffu, mk != 0);
    if ((t & 31) == 0) scount[t >> 5] = __popc(bal);
    __syncthreads();
    if (t == 0) {
        int c = 0;
        for (int i = 0; i < 8; i++) c += scount[i];
        atomicAdd(&g_np, (unsigned)c);
    }
}

// ---------------- K4: per-channel masked sums ----------------
__global__ void k4_stats(const float* __restrict__ x) {
    const int b = blockIdx.z, c = blockIdx.y, chunk = blockIdx.x;  // 4 chunks/plane
    const float* xp = x + (((size_t)(b * CC + c)) << 16);
    const unsigned char* mp = g_mask + (b << 16);
    const int t = threadIdx.x;
    float s1 = 0.f, q1 = 0.f, s2 = 0.f, q2 = 0.f;
#pragma unroll 4
    for (int i = 0; i < 16; i++) {
        int pix = (chunk * 4096 + i * 256 + t) * 4;
        float4 xv = *(const float4*)(xp + pix);
        uchar4 mk = *(const uchar4*)(mp + pix);
        float m, n;
        m = mk.x ? 1.f : 0.f; n = 1.f - m;
        s1 = fmaf(m, xv.x, s1); q1 = fmaf(m * xv.x, xv.x, q1);
        s2 = fmaf(n, xv.x, s2); q2 = fmaf(n * xv.x, xv.x, q2);
        m = mk.y ? 1.f : 0.f; n = 1.f - m;
        s1 = fmaf(m, xv.y, s1); q1 = fmaf(m * xv.y, xv.y, q1);
        s2 = fmaf(n, xv.y, s2); q2 = fmaf(n * xv.y, xv.y, q2);
        m = mk.z ? 1.f : 0.f; n = 1.f - m;
        s1 = fmaf(m, xv.z, s1); q1 = fmaf(m * xv.z, xv.z, q1);
        s2 = fmaf(n, xv.z, s2); q2 = fmaf(n * xv.z, xv.z, q2);
        m = mk.w ? 1.f : 0.f; n = 1.f - m;
        s1 = fmaf(m, xv.w, s1); q1 = fmaf(m * xv.w, xv.w, q1);
        s2 = fmaf(n, xv.w, s2); q2 = fmaf(n * xv.w, xv.w, q2);
    }
#pragma unroll
    for (int o = 16; o; o >>= 1) {
        s1 += __shfl_down_sync(0xffffffffu, s1, o);
        q1 += __shfl_down_sync(0xffffffffu, q1, o);
        s2 += __shfl_down_sync(0xffffffffu, s2, o);
        q2 += __shfl_down_sync(0xffffffffu, q2, o);
    }
    __shared__ float sh[8][4];
    int lane = t & 31, w = t >> 5;
    if (lane == 0) { sh[w][0] = s1; sh[w][1] = q1; sh[w][2] = s2; sh[w][3] = q2; }
    __syncthreads();
    if (t < 4) {
        float v = 0.f;
        for (int i = 0; i < 8; i++) v += sh[i][t];
        atomicAdd(&g_stats[c * 4 + t], (double)v);
    }
}

// ---------------- K5: finalize per-channel params ----------------
__global__ void k5_params() {
    int c = threadIdx.x;
    double s1 = g_stats[c * 4 + 0], q1 = g_stats[c * 4 + 1];
    double s2 = g_stats[c * 4 + 2], q2 = g_stats[c * 4 + 3];
    double np = (double)g_np;
    double nq = (double)TOTPIX - np;
    double Sr1 = np > 0.0 ? np : 1.0;
    double Sr2 = nq > 0.0 ? nq : 1.0;
    double mu1 = s1 / Sr1, mu2 = s2 / Sr2;
    double nt  = (double)TOTPIX;
    double v1 = (q1 - s1 * mu1) / nt;
    double v2 = (q2 - s2 * mu2) / nt;
    if (v1 < 0.0) v1 = 0.0;
    if (v2 < 0.0) v2 = 0.0;
    double a1 = sqrt(Sr1 / nt) / sqrt(v1 + 1e-5);
    double a2 = sqrt(Sr2 / nt) / sqrt(v2 + 1e-5);
    g_params[c * 4 + 0] = (float)mu1; g_params[c * 4 + 1] = (float)a1;
    g_params[c * 4 + 2] = (float)mu2; g_params[c * 4 + 3] = (float)a2;
}

// ---------------- K6: fused output ----------------
__global__ void k6_out(const float* __restrict__ x, float* __restrict__ out) {
    __shared__ float4 sp[CC];
    int t = threadIdx.x;
    if (t < CC) sp[t] = ((const float4*)g_params)[t];
    __syncthreads();
    int tid  = blockIdx.x * blockDim.x + t;
    int base = tid * 4;
    int b    = base >> 16;
    int pix  = base & (MN - 1);
    uchar4 mk = *(const uchar4*)(g_mask + base);
    float4 gm = *(const float4*)(g_gam + base);
    float4 bt = *(const float4*)(g_bet + base);
    float g0 = 1.f + gm.x, g1 = 1.f + gm.y, g2 = 1.f + gm.z, g3 = 1.f + gm.w;
    const float* xb = x   + ((size_t)b << 22) + pix;
    float*       ob = out + ((size_t)b << 22) + pix;
#pragma unroll 4
    for (int c = 0; c < CC; c++) {
        float4 xv = *(const float4*)(xb + ((size_t)c << 16));
        float4 p  = sp[c];
        float4 o;
        float mu, a;
        mu = mk.x ? p.x : p.z; a = mk.x ? p.y : p.w; o.x = (xv.x - mu) * (a * g0) + bt.x;
        mu = mk.y ? p.x : p.z; a = mk.y ? p.y : p.w; o.y = (xv.y - mu) * (a * g1) + bt.y;
        mu = mk.z ? p.x : p.z; a = mk.z ? p.y : p.w; o.z = (xv.z - mu) * (a * g2) + bt.z;
        mu = mk.w ? p.x : p.z; a = mk.w ? p.y : p.w; o.w = (xv.w - mu) * (a * g3) + bt.w;
        *(float4*)(ob + ((size_t)c << 16)) = o;
    }
}

extern "C" void kernel_launch(void* const* d_in, const int* in_sizes, int n_in,
                              void* d_out, int out_size) {
    const float* x  = (const float*)d_in[0];
    const float* w1 = (const float*)d_in[1];
    const float* wg = (const float*)d_in[2];
    const float* bg = (const float*)d_in[3];
    const float* wb = (const float*)d_in[4];
    const float* bb = (const float*)d_in[5];
    float* out = (float*)d_out;

    k0_zero<<<1, 256>>>();
    k1_avgmax<<<TOTPIX / 1024, 256>>>(x);
    dim3 cb(32, 8), cg(8, 32, BN);
    k2_samap<<<cg, cb>>>(w1);
    k3_gb<<<cg, cb>>>(wg, bg, wb, bb);
    k4_stats<<<dim3(4, CC, BN), 256>>>(x);
    k5_params<<<1, CC>>>();
    k6_out<<<TOTPIX / 1024, 256>>>(x, out);
}